// round 6
// baseline (speedup 1.0000x reference)
#include <cuda_runtime.h>
#include <cuda_fp16.h>
#include <cstdint>
#include <math.h>

// Problem constants (fixed by the dataset)
#define N0 30000
#define N1 50000
#define N2 20000
#define NTOT 100000
#define NE 1600000
#define NR 6
#define RN (NR * NTOT)

// ---------------------------------------------------------------------------
// Scratch (static __device__ globals; allocation-free per harness rules)
// ---------------------------------------------------------------------------
__device__ float g_x[(size_t)NTOT * 128];     // concat of projected inputs
__device__ float g_xt1[(size_t)NTOT * 384];   // layer1 per-relation transform
__device__ float g_agg1[(size_t)NTOT * 64];   // layer1 accumulator / h1
__device__ float g_xt2[(size_t)NTOT * 96];    // layer2 per-relation transform
__device__ float g_agg2[(size_t)NTOT * 16];   // layer2 accumulator / h2
__device__ int   g_cnt[RN];
__device__ float g_inv[RN];
__device__ float g_W1[448 * 128];             // [n][k]
__device__ float g_W2[112 * 64];              // [n][k]

// ---------------------------------------------------------------------------
// Small helper kernels
// ---------------------------------------------------------------------------
__global__ void zero_cnt_kernel() {
    int i = blockIdx.x * blockDim.x + threadIdx.x;
    if (i < RN) g_cnt[i] = 0;
}

__global__ void count_kernel(const int* __restrict__ dst, const int* __restrict__ et) {
    int e = blockIdx.x * blockDim.x + threadIdx.x;
    if (e < NE) atomicAdd(&g_cnt[et[e] * NTOT + dst[e]], 1);
}

__global__ void inv_kernel() {
    int i = blockIdx.x * blockDim.x + threadIdx.x;
    if (i < RN) {
        int c = g_cnt[i];
        g_inv[i] = 1.0f / (float)(c > 1 ? c : 1);
    }
}

__global__ void build_w1(const float* __restrict__ comp1, const float* __restrict__ bases1,
                         const float* __restrict__ root1) {
    int idx = blockIdx.x * blockDim.x + threadIdx.x;
    if (idx >= 448 * 128) return;
    int n = idx >> 7, k = idx & 127;
    float v;
    if (n < 384) {
        int r = n >> 6, o = n & 63;
        v = 0.0f;
        for (int b = 0; b < 30; b++)
            v += comp1[r * 30 + b] * bases1[((size_t)b * 128 + k) * 64 + o];
    } else {
        v = root1[k * 64 + (n - 384)];
    }
    g_W1[idx] = v;
}

__global__ void build_w2(const float* __restrict__ comp2, const float* __restrict__ bases2,
                         const float* __restrict__ root2) {
    int idx = blockIdx.x * blockDim.x + threadIdx.x;
    if (idx >= 112 * 64) return;
    int n = idx >> 6, k = idx & 63;
    float v;
    if (n < 96) {
        int r = n >> 4, o = n & 15;
        v = 0.0f;
        for (int b = 0; b < 30; b++)
            v += comp2[r * 30 + b] * bases2[((size_t)b * 64 + k) * 16 + o];
    } else {
        v = root2[k * 16 + (n - 96)];
    }
    g_W2[idx] = v;
}

// ---------------------------------------------------------------------------
// FP16x3 split-precision tensor-core GEMM core.
//   C[m,n] = sum_k A[m,k]*Bw[n,k], fp32 in/out, fp16 hi/lo decomposition:
//   a*b ~= ahi*bhi + ahi*blo + alo*bhi   (error ~2^-22)
// BM=BN=128, BK=32, 256 threads (8 warps: 2 (m) x 4 (n), 64x32 per warp).
// smem layout per row: 16 half2 words, permuted so one thread's BK=32
// fragment slice for a row is a single 16-byte LDS.
// ---------------------------------------------------------------------------
#define BM 128
#define BN 128
#define BK 32

__device__ __forceinline__ void mma_fp16(float* c, unsigned a0, unsigned a1,
                                         unsigned a2, unsigned a3,
                                         unsigned b0, unsigned b1) {
    asm volatile(
        "mma.sync.aligned.m16n8k16.row.col.f32.f16.f16.f32 "
        "{%0,%1,%2,%3}, {%4,%5,%6,%7}, {%8,%9}, {%0,%1,%2,%3};"
        : "+f"(c[0]), "+f"(c[1]), "+f"(c[2]), "+f"(c[3])
        : "r"(a0), "r"(a1), "r"(a2), "r"(a3), "r"(b0), "r"(b1));
}

// 6 MMAs covering hi*hi + hi*lo + lo*hi over both k-halves of the fragments.
__device__ __forceinline__ void mma_x3(float* c,
                                       const uint4& ah0, const uint4& ah1,
                                       const uint4& al0, const uint4& al1,
                                       const uint4& bh,  const uint4& bl) {
    mma_fp16(c, ah0.x, ah1.x, ah0.y, ah1.y, bh.x, bh.y);
    mma_fp16(c, ah0.x, ah1.x, ah0.y, ah1.y, bl.x, bl.y);
    mma_fp16(c, al0.x, al1.x, al0.y, al1.y, bh.x, bh.y);
    mma_fp16(c, ah0.z, ah1.z, ah0.w, ah1.w, bh.z, bh.w);
    mma_fp16(c, ah0.z, ah1.z, ah0.w, ah1.w, bl.z, bl.w);
    mma_fp16(c, al0.z, al1.z, al0.w, al1.w, bh.z, bh.w);
}

__device__ __forceinline__ void split_store(unsigned* hi, unsigned* lo,
                                            int row, int c, float4 v) {
    // c = float4 index within row (0..7); k = 4c..4c+3
    __half hx0 = __float2half_rn(v.x);
    __half hx1 = __float2half_rn(v.y);
    __half hx2 = __float2half_rn(v.z);
    __half hx3 = __float2half_rn(v.w);
    __half lx0 = __float2half_rn(v.x - __half2float(hx0));
    __half lx1 = __float2half_rn(v.y - __half2float(hx1));
    __half lx2 = __float2half_rn(v.z - __half2float(hx2));
    __half lx3 = __float2half_rn(v.w - __half2float(hx3));
    int idx0 = 8 * (c & 1) + 2 * (c >> 2) + ((c >> 1) & 1);
    __half2 h01 = __halves2half2(hx0, hx1);
    __half2 h23 = __halves2half2(hx2, hx3);
    __half2 l01 = __halves2half2(lx0, lx1);
    __half2 l23 = __halves2half2(lx2, lx3);
    hi[row * 16 + idx0]     = *(unsigned*)&h01;
    hi[row * 16 + idx0 + 4] = *(unsigned*)&h23;
    lo[row * 16 + idx0]     = *(unsigned*)&l01;
    lo[row * 16 + idx0 + 4] = *(unsigned*)&l23;
}

__device__ __forceinline__ void gemm_core(
    const float* __restrict__ A, const float* __restrict__ Bw,
    int M, int N, int K, int bm, int bn,
    float* __restrict__ C1, int n1, const float* __restrict__ b1,
    float* __restrict__ C2, const float* __restrict__ b2) {

    __shared__ unsigned Ahi[BM * 16], Alo[BM * 16];
    __shared__ unsigned Bhi[BN * 16], Blo[BN * 16];

    const int tid = threadIdx.x;
    const int wid = tid >> 5;
    const int lane = tid & 31;
    const int wm = wid & 1;
    const int wn = wid >> 1;
    const int g = lane >> 2;
    const int t = lane & 3;

    const int lrow = tid >> 3;        // 0..31, +32 per iter -> 128 rows
    const int lc = tid & 7;           // float4 index in row

    float acc[4][4][4];
    #pragma unroll
    for (int i = 0; i < 4; i++)
        #pragma unroll
        for (int j = 0; j < 4; j++)
            #pragma unroll
            for (int q = 0; q < 4; q++) acc[i][j][q] = 0.0f;

    const float4 z4 = make_float4(0.f, 0.f, 0.f, 0.f);
    float4 sa[4], sb[4];

    // prefetch first k-tile
    #pragma unroll
    for (int i = 0; i < 4; i++) {
        int row = lrow + i * 32;
        sa[i] = (bm + row < M) ? *(const float4*)(A + (size_t)(bm + row) * K + lc * 4) : z4;
        sb[i] = (bn + row < N) ? *(const float4*)(Bw + (size_t)(bn + row) * K + lc * 4) : z4;
    }

    for (int k0 = 0; k0 < K; k0 += BK) {
        #pragma unroll
        for (int i = 0; i < 4; i++) {
            int row = lrow + i * 32;
            split_store(Ahi, Alo, row, lc, sa[i]);
            split_store(Bhi, Blo, row, lc, sb[i]);
        }
        __syncthreads();

        if (k0 + BK < K) {
            #pragma unroll
            for (int i = 0; i < 4; i++) {
                int row = lrow + i * 32;
                sa[i] = (bm + row < M) ? *(const float4*)(A + (size_t)(bm + row) * K + k0 + BK + lc * 4) : z4;
                sb[i] = (bn + row < N) ? *(const float4*)(Bw + (size_t)(bn + row) * K + k0 + BK + lc * 4) : z4;
            }
        }

        uint4 bh[4], bl[4];
        #pragma unroll
        for (int nt = 0; nt < 4; nt++) {
            int cn = wn * 32 + nt * 8 + g;
            bh[nt] = *(const uint4*)&Bhi[cn * 16 + t * 4];
            bl[nt] = *(const uint4*)&Blo[cn * 16 + t * 4];
        }

        #pragma unroll
        for (int mt = 0; mt < 4; mt++) {
            int r = wm * 64 + mt * 16 + g;
            uint4 ah0 = *(const uint4*)&Ahi[r * 16 + t * 4];
            uint4 ah1 = *(const uint4*)&Ahi[(r + 8) * 16 + t * 4];
            uint4 al0 = *(const uint4*)&Alo[r * 16 + t * 4];
            uint4 al1 = *(const uint4*)&Alo[(r + 8) * 16 + t * 4];
            #pragma unroll
            for (int nt = 0; nt < 4; nt++)
                mma_x3(acc[mt][nt], ah0, ah1, al0, al1, bh[nt], bl[nt]);
        }
        __syncthreads();
    }

    // epilogue: c0=C[g][2t], c1=C[g][2t+1], c2=C[g+8][2t], c3=C[g+8][2t+1]
    const int n2w = N - n1;
    #pragma unroll
    for (int mt = 0; mt < 4; mt++) {
        #pragma unroll
        for (int nt = 0; nt < 4; nt++) {
            int col = bn + wn * 32 + nt * 8 + 2 * t;
            if (col >= N) continue;
            #pragma unroll
            for (int half = 0; half < 2; half++) {
                int row = bm + wm * 64 + mt * 16 + g + half * 8;
                if (row >= M) continue;
                float v0 = acc[mt][nt][half * 2 + 0];
                float v1 = acc[mt][nt][half * 2 + 1];
                if (col < n1) {
                    if (b1) { v0 += b1[col]; v1 += b1[col + 1]; }
                    *(float2*)(C1 + (size_t)row * n1 + col) = make_float2(v0, v1);
                } else {
                    int cc = col - n1;
                    if (b2) { v0 += b2[cc]; v1 += b2[cc + 1]; }
                    *(float2*)(C2 + (size_t)row * n2w + cc) = make_float2(v0, v1);
                }
            }
        }
    }
}

// Layer GEMM (split output): grid = (n-tiles, m-tiles)
__global__ __launch_bounds__(256)
void gemm_split(const float* __restrict__ A, const float* __restrict__ Bw,
                int M, int N, int K,
                float* __restrict__ C1, int n1, const float* __restrict__ b1,
                float* __restrict__ C2, const float* __restrict__ b2) {
    gemm_core(A, Bw, M, N, K, blockIdx.y * BM, blockIdx.x * BN, C1, n1, b1, C2, b2);
}

// Fused input projections: grid.y = T0+T1+T2 row tiles, one 128-col output.
__global__ __launch_bounds__(256)
void gemm3_proj(const float* __restrict__ x0, const float* __restrict__ w0, const float* __restrict__ bb0,
                const float* __restrict__ x1, const float* __restrict__ w1, const float* __restrict__ bb1,
                const float* __restrict__ x2, const float* __restrict__ w2, const float* __restrict__ bb2,
                int T0, int T01, float* __restrict__ xb) {
    int tile = blockIdx.y;
    const float* A; const float* Bw; const float* bias;
    int M, K, rowbase, ltile;
    if (tile < T0)        { A = x0; Bw = w0; bias = bb0; M = N0; K = 256; rowbase = 0;       ltile = tile; }
    else if (tile < T01)  { A = x1; Bw = w1; bias = bb1; M = N1; K = 512; rowbase = N0;      ltile = tile - T0; }
    else                  { A = x2; Bw = w2; bias = bb2; M = N2; K = 128; rowbase = N0 + N1; ltile = tile - T01; }
    gemm_core(A, Bw, M, 128, K, ltile * BM, 0,
              xb + (size_t)rowbase * 128, 128, bias, nullptr, nullptr);
}

// ---------------------------------------------------------------------------
// Edge scatter kernels: agg[dst] += inv[type,dst] * xt[src, type*dout .. ]
// ---------------------------------------------------------------------------
__device__ __forceinline__ void red_add_v4(float* addr, float4 v) {
    asm volatile("red.global.add.v4.f32 [%0], {%1, %2, %3, %4};"
                 :: "l"(addr), "f"(v.x), "f"(v.y), "f"(v.z), "f"(v.w)
                 : "memory");
}

__global__ __launch_bounds__(256)
void edge_scatter_64(const int* __restrict__ ei, const int* __restrict__ et) {
    int tglob = blockIdx.x * blockDim.x + threadIdx.x;
    int e = tglob >> 4;
    if (e >= NE) return;
    int lane = tglob & 15;
    int s = ei[e];
    int d = ei[NE + e];
    int r = et[e];
    float w = g_inv[r * NTOT + d];
    float4 v = *(const float4*)(g_xt1 + (size_t)s * 384 + r * 64 + lane * 4);
    red_add_v4(g_agg1 + (size_t)d * 64 + lane * 4,
               make_float4(v.x * w, v.y * w, v.z * w, v.w * w));
}

__global__ __launch_bounds__(256)
void edge_scatter_16(const int* __restrict__ ei, const int* __restrict__ et) {
    int tglob = blockIdx.x * blockDim.x + threadIdx.x;
    int e = tglob >> 2;
    if (e >= NE) return;
    int lane = tglob & 3;
    int s = ei[e];
    int d = ei[NE + e];
    int r = et[e];
    float w = g_inv[r * NTOT + d];
    float4 v = *(const float4*)(g_xt2 + (size_t)s * 96 + r * 16 + lane * 4);
    red_add_v4(g_agg2 + (size_t)d * 16 + lane * 4,
               make_float4(v.x * w, v.y * w, v.z * w, v.w * w));
}

// ---------------------------------------------------------------------------
// Softmax over the first N0 rows (16 cols each)
// ---------------------------------------------------------------------------
__global__ void softmax_kernel(float* __restrict__ out) {
    int row = blockIdx.x * blockDim.x + threadIdx.x;
    if (row >= N0) return;
    const float* p = g_agg2 + (size_t)row * 16;
    float v[16];
    #pragma unroll
    for (int i = 0; i < 4; i++) {
        float4 q = *(const float4*)(p + i * 4);
        v[i * 4 + 0] = q.x; v[i * 4 + 1] = q.y; v[i * 4 + 2] = q.z; v[i * 4 + 3] = q.w;
    }
    float mx = v[0];
    #pragma unroll
    for (int i = 1; i < 16; i++) mx = fmaxf(mx, v[i]);
    float s = 0.0f;
    #pragma unroll
    for (int i = 0; i < 16; i++) { v[i] = expf(v[i] - mx); s += v[i]; }
    float inv = 1.0f / s;
    float* o = out + (size_t)row * 16;
    #pragma unroll
    for (int i = 0; i < 4; i++) {
        float4 q = make_float4(v[i * 4 + 0] * inv, v[i * 4 + 1] * inv,
                               v[i * 4 + 2] * inv, v[i * 4 + 3] * inv);
        *(float4*)(o + i * 4) = q;
    }
}

// ---------------------------------------------------------------------------
// Launcher
// ---------------------------------------------------------------------------
extern "C" void kernel_launch(void* const* d_in, const int* in_sizes, int n_in,
                              void* d_out, int out_size) {
    (void)in_sizes; (void)n_in; (void)out_size;
    const float* x0     = (const float*)d_in[0];
    const float* x1     = (const float*)d_in[1];
    const float* x2     = (const float*)d_in[2];
    const float* lin_w0 = (const float*)d_in[3];
    const float* lin_b0 = (const float*)d_in[4];
    const float* lin_w1 = (const float*)d_in[5];
    const float* lin_b1 = (const float*)d_in[6];
    const float* lin_w2 = (const float*)d_in[7];
    const float* lin_b2 = (const float*)d_in[8];
    const float* bases1 = (const float*)d_in[9];
    const float* comp1  = (const float*)d_in[10];
    const float* root1  = (const float*)d_in[11];
    const float* bias1  = (const float*)d_in[12];
    const float* bases2 = (const float*)d_in[13];
    const float* comp2  = (const float*)d_in[14];
    const float* root2  = (const float*)d_in[15];
    const float* bias2  = (const float*)d_in[16];
    const int*   eidx   = (const int*)d_in[17];
    const int*   etyp   = (const int*)d_in[18];
    float* out = (float*)d_out;

    float *xb, *xt1, *agg1, *xt2, *agg2, *W1, *W2;
    cudaGetSymbolAddress((void**)&xb,   g_x);
    cudaGetSymbolAddress((void**)&xt1,  g_xt1);
    cudaGetSymbolAddress((void**)&agg1, g_agg1);
    cudaGetSymbolAddress((void**)&xt2,  g_xt2);
    cudaGetSymbolAddress((void**)&agg2, g_agg2);
    cudaGetSymbolAddress((void**)&W1,   g_W1);
    cudaGetSymbolAddress((void**)&W2,   g_W2);

    // counts (shared by both layers)
    zero_cnt_kernel<<<(RN + 255) / 256, 256>>>();
    count_kernel<<<(NE + 255) / 256, 256>>>(eidx + NE, etyp);
    inv_kernel<<<(RN + 255) / 256, 256>>>();

    // typed input projections -> g_x (fused single launch)
    const int T0 = (N0 + BM - 1) / BM;        // 235
    const int T1 = (N1 + BM - 1) / BM;        // 391
    const int T2 = (N2 + BM - 1) / BM;        // 157
    gemm3_proj<<<dim3(1, T0 + T1 + T2), 256>>>(
        x0, lin_w0, lin_b0, x1, lin_w1, lin_b1, x2, lin_w2, lin_b2,
        T0, T0 + T1, xb);

    // layer 1: xt1 (relation cols) + agg1 init (root+bias cols)
    build_w1<<<(448 * 128 + 255) / 256, 256>>>(comp1, bases1, root1);
    gemm_split<<<dim3(4, (NTOT + BM - 1) / BM), 256>>>(
        xb, W1, NTOT, 448, 128, xt1, 384, nullptr, agg1, bias1);
    edge_scatter_64<<<(NE * 16) / 256, 256>>>(eidx, etyp);

    // layer 2: xt2 + agg2 init
    build_w2<<<(112 * 64 + 255) / 256, 256>>>(comp2, bases2, root2);
    gemm_split<<<dim3(1, (NTOT + BM - 1) / BM), 256>>>(
        agg1, W2, NTOT, 112, 64, xt2, 96, nullptr, agg2, bias2);
    edge_scatter_16<<<(NE * 4) / 256, 256>>>(eidx, etyp);

    // softmax over author rows
    softmax_kernel<<<(N0 + 255) / 256, 256>>>(out);
}

// round 7
// speedup vs baseline: 1.1203x; 1.1203x over previous
#include <cuda_runtime.h>
#include <cuda_fp16.h>
#include <cstdint>
#include <math.h>

// Problem constants (fixed by the dataset)
#define N0 30000
#define N1 50000
#define N2 20000
#define NTOT 100000
#define NE 1600000
#define NR 6
#define RN (NR * NTOT)

// ---------------------------------------------------------------------------
// Scratch (static __device__ globals; allocation-free per harness rules)
// ---------------------------------------------------------------------------
__device__ float g_x[(size_t)NTOT * 128];     // concat of projected inputs
__device__ float g_xt1[(size_t)NTOT * 384];   // layer1 per-relation transform
__device__ float g_agg1[(size_t)NTOT * 64];   // layer1 accumulator / h1
__device__ float g_xt2[(size_t)NTOT * 96];    // layer2 per-relation transform
__device__ float g_agg2[(size_t)NTOT * 16];   // layer2 accumulator / h2
__device__ int   g_cnt[RN];
__device__ float g_inv[RN];
__device__ float g_W1[448 * 128];             // [n][k]
__device__ float g_W2[112 * 64];              // [n][k]

// ---------------------------------------------------------------------------
// Small helper kernels
// ---------------------------------------------------------------------------
__global__ void zero_cnt_kernel() {
    int i = blockIdx.x * blockDim.x + threadIdx.x;
    if (i < RN) g_cnt[i] = 0;
}

__global__ void count_kernel(const int* __restrict__ dst, const int* __restrict__ et) {
    int e = blockIdx.x * blockDim.x + threadIdx.x;
    if (e < NE) atomicAdd(&g_cnt[et[e] * NTOT + dst[e]], 1);
}

__global__ void inv_kernel() {
    int i = blockIdx.x * blockDim.x + threadIdx.x;
    if (i < RN) {
        int c = g_cnt[i];
        g_inv[i] = 1.0f / (float)(c > 1 ? c : 1);
    }
}

__global__ void build_w1(const float* __restrict__ comp1, const float* __restrict__ bases1,
                         const float* __restrict__ root1) {
    int idx = blockIdx.x * blockDim.x + threadIdx.x;
    if (idx >= 448 * 128) return;
    int n = idx >> 7, k = idx & 127;
    float v;
    if (n < 384) {
        int r = n >> 6, o = n & 63;
        v = 0.0f;
        for (int b = 0; b < 30; b++)
            v += comp1[r * 30 + b] * bases1[((size_t)b * 128 + k) * 64 + o];
    } else {
        v = root1[k * 64 + (n - 384)];
    }
    g_W1[idx] = v;
}

__global__ void build_w2(const float* __restrict__ comp2, const float* __restrict__ bases2,
                         const float* __restrict__ root2) {
    int idx = blockIdx.x * blockDim.x + threadIdx.x;
    if (idx >= 112 * 64) return;
    int n = idx >> 6, k = idx & 63;
    float v;
    if (n < 96) {
        int r = n >> 4, o = n & 15;
        v = 0.0f;
        for (int b = 0; b < 30; b++)
            v += comp2[r * 30 + b] * bases2[((size_t)b * 64 + k) * 16 + o];
    } else {
        v = root2[k * 16 + (n - 96)];
    }
    g_W2[idx] = v;
}

// ---------------------------------------------------------------------------
// FP16x3 split-precision tensor-core GEMM core.
//   C[m,n] = sum_k A[m,k]*Bw[n,k], fp32 in/out, fp16 hi/lo decomposition:
//   a*b ~= ahi*bhi + ahi*blo + alo*bhi   (error ~2^-22)
// BM=128, BN=64, BK=32; 256 threads = 8 warps as 4(m) x 2(n), 32x32/warp.
// __launch_bounds__(256,2) -> regs<=128 -> 2 CTAs/SM (occupancy fix vs R6).
// smem layout per row: 16 half2 words, permuted so one thread's BK=32
// fragment slice for a row is a single 16-byte LDS.
// ---------------------------------------------------------------------------
#define BM 128
#define BN 64
#define BK 32

__device__ __forceinline__ void mma_fp16(float* c, unsigned a0, unsigned a1,
                                         unsigned a2, unsigned a3,
                                         unsigned b0, unsigned b1) {
    asm volatile(
        "mma.sync.aligned.m16n8k16.row.col.f32.f16.f16.f32 "
        "{%0,%1,%2,%3}, {%4,%5,%6,%7}, {%8,%9}, {%0,%1,%2,%3};"
        : "+f"(c[0]), "+f"(c[1]), "+f"(c[2]), "+f"(c[3])
        : "r"(a0), "r"(a1), "r"(a2), "r"(a3), "r"(b0), "r"(b1));
}

// 6 MMAs covering hi*hi + hi*lo + lo*hi over both k-halves of the fragments.
__device__ __forceinline__ void mma_x3(float* c,
                                       const uint4& ah0, const uint4& ah1,
                                       const uint4& al0, const uint4& al1,
                                       const uint4& bh,  const uint4& bl) {
    mma_fp16(c, ah0.x, ah1.x, ah0.y, ah1.y, bh.x, bh.y);
    mma_fp16(c, ah0.x, ah1.x, ah0.y, ah1.y, bl.x, bl.y);
    mma_fp16(c, al0.x, al1.x, al0.y, al1.y, bh.x, bh.y);
    mma_fp16(c, ah0.z, ah1.z, ah0.w, ah1.w, bh.z, bh.w);
    mma_fp16(c, ah0.z, ah1.z, ah0.w, ah1.w, bl.z, bl.w);
    mma_fp16(c, al0.z, al1.z, al0.w, al1.w, bh.z, bh.w);
}

__device__ __forceinline__ void split_store(unsigned* hi, unsigned* lo,
                                            int row, int c, float4 v) {
    // c = float4 index within row (0..7); k = 4c..4c+3
    __half hx0 = __float2half_rn(v.x);
    __half hx1 = __float2half_rn(v.y);
    __half hx2 = __float2half_rn(v.z);
    __half hx3 = __float2half_rn(v.w);
    __half lx0 = __float2half_rn(v.x - __half2float(hx0));
    __half lx1 = __float2half_rn(v.y - __half2float(hx1));
    __half lx2 = __float2half_rn(v.z - __half2float(hx2));
    __half lx3 = __float2half_rn(v.w - __half2float(hx3));
    int idx0 = 8 * (c & 1) + 2 * (c >> 2) + ((c >> 1) & 1);
    __half2 h01 = __halves2half2(hx0, hx1);
    __half2 h23 = __halves2half2(hx2, hx3);
    __half2 l01 = __halves2half2(lx0, lx1);
    __half2 l23 = __halves2half2(lx2, lx3);
    hi[row * 16 + idx0]     = *(unsigned*)&h01;
    hi[row * 16 + idx0 + 4] = *(unsigned*)&h23;
    lo[row * 16 + idx0]     = *(unsigned*)&l01;
    lo[row * 16 + idx0 + 4] = *(unsigned*)&l23;
}

__device__ __forceinline__ void gemm_core(
    const float* __restrict__ A, const float* __restrict__ Bw,
    int M, int N, int K, int bm, int bn,
    float* __restrict__ C1, int n1, const float* __restrict__ b1,
    float* __restrict__ C2, const float* __restrict__ b2) {

    __shared__ unsigned Ahi[BM * 16], Alo[BM * 16];
    __shared__ unsigned Bhi[BN * 16], Blo[BN * 16];

    const int tid = threadIdx.x;
    const int wid = tid >> 5;
    const int lane = tid & 31;
    const int wm = wid & 3;           // 4 m-warps  -> 32 rows each
    const int wn = wid >> 2;          // 2 n-warps  -> 32 cols each
    const int g = lane >> 2;          // 0..7
    const int t = lane & 3;           // 0..3

    const int lrow = tid >> 3;        // 0..31, +32 per iter
    const int lc = tid & 7;           // float4 index in row

    float acc[2][4][4];
    #pragma unroll
    for (int i = 0; i < 2; i++)
        #pragma unroll
        for (int j = 0; j < 4; j++)
            #pragma unroll
            for (int q = 0; q < 4; q++) acc[i][j][q] = 0.0f;

    const float4 z4 = make_float4(0.f, 0.f, 0.f, 0.f);
    float4 sa[4], sb[2];

    // prefetch first k-tile
    #pragma unroll
    for (int i = 0; i < 4; i++) {
        int row = lrow + i * 32;
        sa[i] = (bm + row < M) ? *(const float4*)(A + (size_t)(bm + row) * K + lc * 4) : z4;
    }
    #pragma unroll
    for (int i = 0; i < 2; i++) {
        int row = lrow + i * 32;
        sb[i] = (bn + row < N) ? *(const float4*)(Bw + (size_t)(bn + row) * K + lc * 4) : z4;
    }

    for (int k0 = 0; k0 < K; k0 += BK) {
        #pragma unroll
        for (int i = 0; i < 4; i++)
            split_store(Ahi, Alo, lrow + i * 32, lc, sa[i]);
        #pragma unroll
        for (int i = 0; i < 2; i++)
            split_store(Bhi, Blo, lrow + i * 32, lc, sb[i]);
        __syncthreads();

        if (k0 + BK < K) {
            #pragma unroll
            for (int i = 0; i < 4; i++) {
                int row = lrow + i * 32;
                sa[i] = (bm + row < M) ? *(const float4*)(A + (size_t)(bm + row) * K + k0 + BK + lc * 4) : z4;
            }
            #pragma unroll
            for (int i = 0; i < 2; i++) {
                int row = lrow + i * 32;
                sb[i] = (bn + row < N) ? *(const float4*)(Bw + (size_t)(bn + row) * K + k0 + BK + lc * 4) : z4;
            }
        }

        uint4 bh[4], bl[4];
        #pragma unroll
        for (int nt = 0; nt < 4; nt++) {
            int cn = wn * 32 + nt * 8 + g;
            bh[nt] = *(const uint4*)&Bhi[cn * 16 + t * 4];
            bl[nt] = *(const uint4*)&Blo[cn * 16 + t * 4];
        }

        #pragma unroll
        for (int mt = 0; mt < 2; mt++) {
            int r = wm * 32 + mt * 16 + g;
            uint4 ah0 = *(const uint4*)&Ahi[r * 16 + t * 4];
            uint4 ah1 = *(const uint4*)&Ahi[(r + 8) * 16 + t * 4];
            uint4 al0 = *(const uint4*)&Alo[r * 16 + t * 4];
            uint4 al1 = *(const uint4*)&Alo[(r + 8) * 16 + t * 4];
            #pragma unroll
            for (int nt = 0; nt < 4; nt++)
                mma_x3(acc[mt][nt], ah0, ah1, al0, al1, bh[nt], bl[nt]);
        }
        __syncthreads();
    }

    // epilogue: c0=C[g][2t], c1=C[g][2t+1], c2=C[g+8][2t], c3=C[g+8][2t+1]
    const int n2w = N - n1;
    #pragma unroll
    for (int mt = 0; mt < 2; mt++) {
        #pragma unroll
        for (int nt = 0; nt < 4; nt++) {
            int col = bn + wn * 32 + nt * 8 + 2 * t;
            if (col >= N) continue;
            #pragma unroll
            for (int half = 0; half < 2; half++) {
                int row = bm + wm * 32 + mt * 16 + g + half * 8;
                if (row >= M) continue;
                float v0 = acc[mt][nt][half * 2 + 0];
                float v1 = acc[mt][nt][half * 2 + 1];
                if (col < n1) {
                    if (b1) { v0 += b1[col]; v1 += b1[col + 1]; }
                    *(float2*)(C1 + (size_t)row * n1 + col) = make_float2(v0, v1);
                } else {
                    int cc = col - n1;
                    if (b2) { v0 += b2[cc]; v1 += b2[cc + 1]; }
                    *(float2*)(C2 + (size_t)row * n2w + cc) = make_float2(v0, v1);
                }
            }
        }
    }
}

// Layer GEMM (split output): grid = (n-tiles, m-tiles)
__global__ __launch_bounds__(256, 2)
void gemm_split(const float* __restrict__ A, const float* __restrict__ Bw,
                int M, int N, int K,
                float* __restrict__ C1, int n1, const float* __restrict__ b1,
                float* __restrict__ C2, const float* __restrict__ b2) {
    gemm_core(A, Bw, M, N, K, blockIdx.y * BM, blockIdx.x * BN, C1, n1, b1, C2, b2);
}

// Fused input projections: grid = (2 n-tiles, T0+T1+T2 row tiles).
__global__ __launch_bounds__(256, 2)
void gemm3_proj(const float* __restrict__ x0, const float* __restrict__ w0, const float* __restrict__ bb0,
                const float* __restrict__ x1, const float* __restrict__ w1, const float* __restrict__ bb1,
                const float* __restrict__ x2, const float* __restrict__ w2, const float* __restrict__ bb2,
                int T0, int T01, float* __restrict__ xb) {
    int tile = blockIdx.y;
    const float* A; const float* Bw; const float* bias;
    int M, K, rowbase, ltile;
    if (tile < T0)        { A = x0; Bw = w0; bias = bb0; M = N0; K = 256; rowbase = 0;       ltile = tile; }
    else if (tile < T01)  { A = x1; Bw = w1; bias = bb1; M = N1; K = 512; rowbase = N0;      ltile = tile - T0; }
    else                  { A = x2; Bw = w2; bias = bb2; M = N2; K = 128; rowbase = N0 + N1; ltile = tile - T01; }
    gemm_core(A, Bw, M, 128, K, ltile * BM, blockIdx.x * BN,
              xb + (size_t)rowbase * 128, 128, bias, nullptr, nullptr);
}

// ---------------------------------------------------------------------------
// Edge scatter kernels: agg[dst] += inv[type,dst] * xt[src, type*dout .. ]
// ---------------------------------------------------------------------------
__device__ __forceinline__ void red_add_v4(float* addr, float4 v) {
    asm volatile("red.global.add.v4.f32 [%0], {%1, %2, %3, %4};"
                 :: "l"(addr), "f"(v.x), "f"(v.y), "f"(v.z), "f"(v.w)
                 : "memory");
}

__global__ __launch_bounds__(256)
void edge_scatter_64(const int* __restrict__ ei, const int* __restrict__ et) {
    int tglob = blockIdx.x * blockDim.x + threadIdx.x;
    int e = tglob >> 4;
    if (e >= NE) return;
    int lane = tglob & 15;
    int s = ei[e];
    int d = ei[NE + e];
    int r = et[e];
    float w = g_inv[r * NTOT + d];
    float4 v = *(const float4*)(g_xt1 + (size_t)s * 384 + r * 64 + lane * 4);
    red_add_v4(g_agg1 + (size_t)d * 64 + lane * 4,
               make_float4(v.x * w, v.y * w, v.z * w, v.w * w));
}

__global__ __launch_bounds__(256)
void edge_scatter_16(const int* __restrict__ ei, const int* __restrict__ et) {
    int tglob = blockIdx.x * blockDim.x + threadIdx.x;
    int e = tglob >> 2;
    if (e >= NE) return;
    int lane = tglob & 3;
    int s = ei[e];
    int d = ei[NE + e];
    int r = et[e];
    float w = g_inv[r * NTOT + d];
    float4 v = *(const float4*)(g_xt2 + (size_t)s * 96 + r * 16 + lane * 4);
    red_add_v4(g_agg2 + (size_t)d * 16 + lane * 4,
               make_float4(v.x * w, v.y * w, v.z * w, v.w * w));
}

// ---------------------------------------------------------------------------
// Softmax over the first N0 rows (16 cols each)
// ---------------------------------------------------------------------------
__global__ void softmax_kernel(float* __restrict__ out) {
    int row = blockIdx.x * blockDim.x + threadIdx.x;
    if (row >= N0) return;
    const float* p = g_agg2 + (size_t)row * 16;
    float v[16];
    #pragma unroll
    for (int i = 0; i < 4; i++) {
        float4 q = *(const float4*)(p + i * 4);
        v[i * 4 + 0] = q.x; v[i * 4 + 1] = q.y; v[i * 4 + 2] = q.z; v[i * 4 + 3] = q.w;
    }
    float mx = v[0];
    #pragma unroll
    for (int i = 1; i < 16; i++) mx = fmaxf(mx, v[i]);
    float s = 0.0f;
    #pragma unroll
    for (int i = 0; i < 16; i++) { v[i] = expf(v[i] - mx); s += v[i]; }
    float inv = 1.0f / s;
    float* o = out + (size_t)row * 16;
    #pragma unroll
    for (int i = 0; i < 4; i++) {
        float4 q = make_float4(v[i * 4 + 0] * inv, v[i * 4 + 1] * inv,
                               v[i * 4 + 2] * inv, v[i * 4 + 3] * inv);
        *(float4*)(o + i * 4) = q;
    }
}

// ---------------------------------------------------------------------------
// Launcher
// ---------------------------------------------------------------------------
extern "C" void kernel_launch(void* const* d_in, const int* in_sizes, int n_in,
                              void* d_out, int out_size) {
    (void)in_sizes; (void)n_in; (void)out_size;
    const float* x0     = (const float*)d_in[0];
    const float* x1     = (const float*)d_in[1];
    const float* x2     = (const float*)d_in[2];
    const float* lin_w0 = (const float*)d_in[3];
    const float* lin_b0 = (const float*)d_in[4];
    const float* lin_w1 = (const float*)d_in[5];
    const float* lin_b1 = (const float*)d_in[6];
    const float* lin_w2 = (const float*)d_in[7];
    const float* lin_b2 = (const float*)d_in[8];
    const float* bases1 = (const float*)d_in[9];
    const float* comp1  = (const float*)d_in[10];
    const float* root1  = (const float*)d_in[11];
    const float* bias1  = (const float*)d_in[12];
    const float* bases2 = (const float*)d_in[13];
    const float* comp2  = (const float*)d_in[14];
    const float* root2  = (const float*)d_in[15];
    const float* bias2  = (const float*)d_in[16];
    const int*   eidx   = (const int*)d_in[17];
    const int*   etyp   = (const int*)d_in[18];
    float* out = (float*)d_out;

    float *xb, *xt1, *agg1, *xt2, *agg2, *W1, *W2;
    cudaGetSymbolAddress((void**)&xb,   g_x);
    cudaGetSymbolAddress((void**)&xt1,  g_xt1);
    cudaGetSymbolAddress((void**)&agg1, g_agg1);
    cudaGetSymbolAddress((void**)&xt2,  g_xt2);
    cudaGetSymbolAddress((void**)&agg2, g_agg2);
    cudaGetSymbolAddress((void**)&W1,   g_W1);
    cudaGetSymbolAddress((void**)&W2,   g_W2);

    // counts (shared by both layers)
    zero_cnt_kernel<<<(RN + 255) / 256, 256>>>();
    count_kernel<<<(NE + 255) / 256, 256>>>(eidx + NE, etyp);
    inv_kernel<<<(RN + 255) / 256, 256>>>();

    // typed input projections -> g_x (fused single launch)
    const int T0 = (N0 + BM - 1) / BM;        // 235
    const int T1 = (N1 + BM - 1) / BM;        // 391
    const int T2 = (N2 + BM - 1) / BM;        // 157
    gemm3_proj<<<dim3(2, T0 + T1 + T2), 256>>>(
        x0, lin_w0, lin_b0, x1, lin_w1, lin_b1, x2, lin_w2, lin_b2,
        T0, T0 + T1, xb);

    // layer 1: xt1 (relation cols) + agg1 init (root+bias cols)
    build_w1<<<(448 * 128 + 255) / 256, 256>>>(comp1, bases1, root1);
    gemm_split<<<dim3(7, (NTOT + BM - 1) / BM), 256>>>(
        xb, W1, NTOT, 448, 128, xt1, 384, nullptr, agg1, bias1);
    edge_scatter_64<<<(NE * 16) / 256, 256>>>(eidx, etyp);

    // layer 2: xt2 + agg2 init
    build_w2<<<(112 * 64 + 255) / 256, 256>>>(comp2, bases2, root2);
    gemm_split<<<dim3(2, (NTOT + BM - 1) / BM), 256>>>(
        agg1, W2, NTOT, 112, 64, xt2, 96, nullptr, agg2, bias2);
    edge_scatter_16<<<(NE * 4) / 256, 256>>>(eidx, etyp);

    // softmax over author rows
    softmax_kernel<<<(N0 + 255) / 256, 256>>>(out);
}